// round 11
// baseline (speedup 1.0000x reference)
#include <cuda_runtime.h>
#include <stdint.h>

#define HIDDEN 128
#define NRAD   6
#define MAXE   2000000
#define MAXN   100352          // a bit over 100000
#define SCAN_B 1024

// ---- static scratch (no dynamic allocation allowed) ----
__device__ int d_count[MAXN];
__device__ int d_cursor[MAXN];
__device__ int d_start[MAXN + 1];
__device__ int d_bsum[(MAXN + SCAN_B - 1) / SCAN_B];
__device__ int d_bpre[(MAXN + SCAN_B - 1) / SCAN_B];
__device__ int d_perm[MAXE];

// ======================= sort passes =======================

__global__ void zero_count_kernel(int n) {
    int i = blockIdx.x * blockDim.x + threadIdx.x;
    if (i < n) d_count[i] = 0;
}

__global__ void hist_kernel(const int* __restrict__ idx, int E) {
    int i = blockIdx.x * blockDim.x + threadIdx.x;
    int stride = gridDim.x * blockDim.x;
    for (int e = i; e < E; e += stride)
        atomicAdd(&d_count[idx[e]], 1);
}

// block-local exclusive scan (Hillis-Steele in smem), blocksum out
__global__ void scan1_kernel(int n) {
    __shared__ int sh[SCAN_B];
    int tid = threadIdx.x;
    int i = blockIdx.x * SCAN_B + tid;
    int v = (i < n) ? d_count[i] : 0;
    sh[tid] = v;
    __syncthreads();
#pragma unroll
    for (int off = 1; off < SCAN_B; off <<= 1) {
        int t = (tid >= off) ? sh[tid - off] : 0;
        __syncthreads();
        sh[tid] += t;
        __syncthreads();
    }
    if (i < n) d_start[i] = sh[tid] - v;         // exclusive within block
    if (tid == SCAN_B - 1) d_bsum[blockIdx.x] = sh[tid];
}

__global__ void scan2_kernel(int nblk) {
    if (threadIdx.x == 0 && blockIdx.x == 0) {
        int acc = 0;
        for (int b = 0; b < nblk; ++b) { d_bpre[b] = acc; acc += d_bsum[b]; }
    }
}

__global__ void scan3_kernel(int n, int E) {
    int tid = threadIdx.x;
    int i = blockIdx.x * SCAN_B + tid;
    if (i < n) {
        int v = d_start[i] + d_bpre[blockIdx.x];
        d_start[i]  = v;
        d_cursor[i] = v;
    }
    if (i == 0) d_start[n] = E;
}

__global__ void build_perm_kernel(const int* __restrict__ idx, int E) {
    int i = blockIdx.x * blockDim.x + threadIdx.x;
    int stride = gridDim.x * blockDim.x;
    for (int e = i; e < E; e += stride) {
        int nd = idx[e];
        int p = atomicAdd(&d_cursor[nd], 1);
        d_perm[p] = e;
    }
}

// ======================= gather pass =======================
// One warp per node. lane owns channels [4*lane, 4*lane+4).
// Accumulates all of the node's edge messages in registers; single store.
__global__ void __launch_bounds__(256, 4)
gather_kernel(const float* __restrict__ x,
              const float* __restrict__ rbf,
              const float* __restrict__ W,
              float* __restrict__ out,
              int n)
{
    const int lane  = threadIdx.x & 31;
    const int wid   = (blockIdx.x * blockDim.x + threadIdx.x) >> 5;
    const int nwarp = (gridDim.x * blockDim.x) >> 5;

    // W: this lane's 4 channel rows (24 floats) in registers.
    const int hbase = lane * 4;
    float w00,w01,w02,w03,w04,w05;
    float w10,w11,w12,w13,w14,w15;
    float w20,w21,w22,w23,w24,w25;
    float w30,w31,w32,w33,w34,w35;
    {
        const float* p = W + hbase * NRAD;
        w00=p[0];  w01=p[1];  w02=p[2];  w03=p[3];  w04=p[4];  w05=p[5];
        w10=p[6];  w11=p[7];  w12=p[8];  w13=p[9];  w14=p[10]; w15=p[11];
        w20=p[12]; w21=p[13]; w22=p[14]; w23=p[15]; w24=p[16]; w25=p[17];
        w30=p[18]; w31=p[19]; w32=p[20]; w33=p[21]; w34=p[22]; w35=p[23];
    }

    const float4* __restrict__ x4   = reinterpret_cast<const float4*>(x);
    const float2* __restrict__ rbf2 = reinterpret_cast<const float2*>(rbf);

    for (int node = wid; node < n; node += nwarp) {
        const int s = d_start[node];
        const int t = d_start[node + 1];

        float a0 = 0.f, a1 = 0.f, a2 = 0.f, a3 = 0.f;

        if (s < t) {
            // pipeline depth 2 over this node's edges
            int    ed_c = d_perm[s];
            float2 r0c = rbf2[3 * (size_t)ed_c];
            float2 r1c = rbf2[3 * (size_t)ed_c + 1];
            float2 r2c = rbf2[3 * (size_t)ed_c + 2];
            float4 xc  = __ldcs(x4 + (size_t)ed_c * 32 + lane);

            for (int k = s; k < t; ++k) {
                int    ed_n = 0;
                float2 r0n, r1n, r2n;
                float4 xn;
                const bool more = (k + 1 < t);
                if (more) {
                    ed_n = d_perm[k + 1];
                    r0n = rbf2[3 * (size_t)ed_n];
                    r1n = rbf2[3 * (size_t)ed_n + 1];
                    r2n = rbf2[3 * (size_t)ed_n + 2];
                    xn  = __ldcs(x4 + (size_t)ed_n * 32 + lane);
                }

                float c0 = fmaf(r0c.x,w00,fmaf(r0c.y,w01,fmaf(r1c.x,w02,
                           fmaf(r1c.y,w03,fmaf(r2c.x,w04,r2c.y*w05)))));
                float c1 = fmaf(r0c.x,w10,fmaf(r0c.y,w11,fmaf(r1c.x,w12,
                           fmaf(r1c.y,w13,fmaf(r2c.x,w14,r2c.y*w15)))));
                float c2 = fmaf(r0c.x,w20,fmaf(r0c.y,w21,fmaf(r1c.x,w22,
                           fmaf(r1c.y,w23,fmaf(r2c.x,w24,r2c.y*w25)))));
                float c3 = fmaf(r0c.x,w30,fmaf(r0c.y,w31,fmaf(r1c.x,w32,
                           fmaf(r1c.y,w33,fmaf(r2c.x,w34,r2c.y*w35)))));

                a0 = fmaf(c0, xc.x, a0);
                a1 = fmaf(c1, xc.y, a1);
                a2 = fmaf(c2, xc.z, a2);
                a3 = fmaf(c3, xc.w, a3);

                if (more) {
                    r0c = r0n; r1c = r1n; r2c = r2n; xc = xn;
                }
            }
        }

        float4 res = make_float4(a0, a1, a2, a3);
        __stcs(reinterpret_cast<float4*>(out + (size_t)node * HIDDEN + hbase), res);
    }
}

// ======================= fallback (atomic path, proven R6) =======================

__global__ void zero_out_kernel(float4* __restrict__ out, int n4) {
    int idx = blockIdx.x * blockDim.x + threadIdx.x;
    int stride = gridDim.x * blockDim.x;
    for (int k = idx; k < n4; k += stride)
        out[k] = make_float4(0.f, 0.f, 0.f, 0.f);
}

__global__ void __launch_bounds__(256, 5)
atomic_fallback_kernel(const float* __restrict__ x,
                       const float* __restrict__ rbf,
                       const float* __restrict__ W,
                       const int* __restrict__ idx,
                       float* __restrict__ out,
                       int E)
{
    const int lane  = threadIdx.x & 31;
    const int wid   = (blockIdx.x * blockDim.x + threadIdx.x) >> 5;
    const int nwarp = (gridDim.x * blockDim.x) >> 5;

    const int hbase = lane * 4;
    float w[4][NRAD];
#pragma unroll
    for (int j = 0; j < 4; ++j)
#pragma unroll
        for (int r = 0; r < NRAD; ++r)
            w[j][r] = W[(hbase + j) * NRAD + r];

    const float4* __restrict__ x4 = reinterpret_cast<const float4*>(x);
    const float2* __restrict__ rbf2 = reinterpret_cast<const float2*>(rbf);

    for (int e = wid; e < E; e += nwarp) {
        int node = idx[e];
        float2 f0 = rbf2[3 * (size_t)e];
        float2 f1 = rbf2[3 * (size_t)e + 1];
        float2 f2 = rbf2[3 * (size_t)e + 2];
        float4 xv = __ldcs(x4 + (size_t)e * 32 + lane);

        float m[4];
#pragma unroll
        for (int j = 0; j < 4; ++j)
            m[j] = fmaf(f0.x, w[j][0], fmaf(f0.y, w[j][1], fmaf(f1.x, w[j][2],
                   fmaf(f1.y, w[j][3], fmaf(f2.x, w[j][4], f2.y * w[j][5])))));

        float* dst = out + (size_t)node * HIDDEN + hbase;
        asm volatile("red.global.add.v4.f32 [%0], {%1, %2, %3, %4};"
                     :: "l"(dst), "f"(m[0] * xv.x), "f"(m[1] * xv.y),
                        "f"(m[2] * xv.z), "f"(m[3] * xv.w) : "memory");
    }
}

// ======================= launch =======================

extern "C" void kernel_launch(void* const* d_in, const int* in_sizes, int n_in,
                              void* d_out, int out_size)
{
    const float* x   = (const float*)d_in[0];   // [E, 128]
    const float* rbf = (const float*)d_in[1];   // [E, 6]
    const float* W   = (const float*)d_in[2];   // [128, 6]
    const int*   idx = (const int*)d_in[3];     // [E] int32
    float*       out = (float*)d_out;           // [num_nodes, 128]

    const int E = in_sizes[0] / HIDDEN;
    const int n = out_size / HIDDEN;            // num_nodes

    if (E > MAXE || n > MAXN) {
        // fallback: atomic scatter path
        int n4 = out_size / 4;
        int zb = (n4 + 255) / 256; if (zb > 8192) zb = 8192;
        zero_out_kernel<<<zb, 256>>>((float4*)out, n4);
        int blocks = 148 * 5;
        int mx = (E + 7) / 8; if (mx < 1) mx = 1;
        if (blocks > mx) blocks = mx;
        atomic_fallback_kernel<<<blocks, 256>>>(x, rbf, W, idx, out, E);
        return;
    }

    const int nblk = (n + SCAN_B - 1) / SCAN_B;

    // 1. zero histogram counters
    zero_count_kernel<<<(n + 255) / 256, 256>>>(n);
    // 2. node-degree histogram
    hist_kernel<<<592, 256>>>(idx, E);
    // 3-5. exclusive scan of degrees -> d_start, d_cursor
    scan1_kernel<<<nblk, SCAN_B>>>(n);
    scan2_kernel<<<1, 32>>>(nblk);
    scan3_kernel<<<nblk, SCAN_B>>>(n, E);
    // 6. build permutation (edges sorted by node)
    build_perm_kernel<<<592, 256>>>(idx, E);
    // 7. gather: warp per node, register accumulation, single store per row
    {
        int threads = 256;                     // 8 warps
        int blocks = (n + 7) / 8;              // warp per node
        gather_kernel<<<blocks, threads>>>(x, rbf, W, out, n);
    }
}

// round 12
// speedup vs baseline: 1.6512x; 1.6512x over previous
#include <cuda_runtime.h>
#include <stdint.h>

#define HIDDEN 128
#define NRAD   6

__global__ void zero_out_kernel(float4* __restrict__ out, int n4) {
    int idx = blockIdx.x * blockDim.x + threadIdx.x;
    int stride = gridDim.x * blockDim.x;
    for (int k = idx; k < n4; k += stride)
        out[k] = make_float4(0.f, 0.f, 0.f, 0.f);
}

// One warp processes a contiguous chunk of edge PAIRS, 2 edges per iteration,
// with both next-pair x rows prefetched (2 LDG.128 in flight per warp).
// lane owns channels [4*lane, 4*lane+4). W register-resident.
// REDs carry an L2::evict_last hint so the 51MB output stays L2-resident.
__global__ void __launch_bounds__(128, 8)
fused_rbf_scatter_kernel(const float* __restrict__ x,
                         const float* __restrict__ rbf,
                         const float* __restrict__ W,   // [HIDDEN, NRAD] row-major
                         const int* __restrict__ idx,   // int32 edge indices
                         float* __restrict__ out,
                         int E)
{
    const int lane  = threadIdx.x & 31;
    const int wid   = (blockIdx.x * blockDim.x + threadIdx.x) >> 5;
    const int nwarp = (gridDim.x * blockDim.x) >> 5;

    // evict_last policy for the atomic destination (keep out resident in L2)
    uint64_t pol;
    asm("createpolicy.fractional.L2::evict_last.b64 %0, 1.0;" : "=l"(pol));

    // This lane's 4 rows of W (24 floats) in registers, loaded once.
    const int hbase = lane * 4;
    float w00,w01,w02,w03,w04,w05;
    float w10,w11,w12,w13,w14,w15;
    float w20,w21,w22,w23,w24,w25;
    float w30,w31,w32,w33,w34,w35;
    {
        const float* p = W + hbase * NRAD;
        w00=p[0];  w01=p[1];  w02=p[2];  w03=p[3];  w04=p[4];  w05=p[5];
        w10=p[6];  w11=p[7];  w12=p[8];  w13=p[9];  w14=p[10]; w15=p[11];
        w20=p[12]; w21=p[13]; w22=p[14]; w23=p[15]; w24=p[16]; w25=p[17];
        w30=p[18]; w31=p[19]; w32=p[20]; w33=p[21]; w34=p[22]; w35=p[23];
    }

    const float4* __restrict__ x4   = reinterpret_cast<const float4*>(x);
    const float4* __restrict__ rbf4 = reinterpret_cast<const float4*>(rbf);
    const int2*   __restrict__ idx2 = reinterpret_cast<const int2*>(idx);

    const int pairsFull = E >> 1;
    const int chunk = (pairsFull + nwarp - 1) / nwarp;
    int p    = wid * chunk;
    int pend = p + chunk;
    if (pend > pairsFull) pend = pairsFull;

    if (p < pend) {
        float4 cur0 = __ldcs(x4 + (size_t)(2 * p)     * (HIDDEN / 4) + lane);
        float4 cur1 = __ldcs(x4 + (size_t)(2 * p + 1) * (HIDDEN / 4) + lane);

        for (; p < pend; ++p) {
            // ---- prefetch next pair's x rows (2 LDG.128 in flight) ----
            float4 nxt0 = cur0, nxt1 = cur1;
            if (p + 1 < pend) {
                nxt0 = __ldcs(x4 + (size_t)(2 * p + 2) * (HIDDEN / 4) + lane);
                nxt1 = __ldcs(x4 + (size_t)(2 * p + 3) * (HIDDEN / 4) + lane);
            }

            int2   nodes = __ldcs(idx2 + p);
            float4 f0 = __ldcs(rbf4 + 3 * (size_t)p);
            float4 f1 = __ldcs(rbf4 + 3 * (size_t)p + 1);
            float4 f2 = __ldcs(rbf4 + 3 * (size_t)p + 2);

            // edge0 coefficients: rbf = {f0.x,f0.y,f0.z,f0.w,f1.x,f1.y}
            float c0 = fmaf(f0.x, w00, fmaf(f0.y, w01, fmaf(f0.z, w02,
                       fmaf(f0.w, w03, fmaf(f1.x, w04, f1.y * w05)))));
            float c1 = fmaf(f0.x, w10, fmaf(f0.y, w11, fmaf(f0.z, w12,
                       fmaf(f0.w, w13, fmaf(f1.x, w14, f1.y * w15)))));
            float c2 = fmaf(f0.x, w20, fmaf(f0.y, w21, fmaf(f0.z, w22,
                       fmaf(f0.w, w23, fmaf(f1.x, w24, f1.y * w25)))));
            float c3 = fmaf(f0.x, w30, fmaf(f0.y, w31, fmaf(f0.z, w32,
                       fmaf(f0.w, w33, fmaf(f1.x, w34, f1.y * w35)))));

            // edge1 coefficients: rbf = {f1.z,f1.w,f2.x,f2.y,f2.z,f2.w}
            float d0 = fmaf(f1.z, w00, fmaf(f1.w, w01, fmaf(f2.x, w02,
                       fmaf(f2.y, w03, fmaf(f2.z, w04, f2.w * w05)))));
            float d1 = fmaf(f1.z, w10, fmaf(f1.w, w11, fmaf(f2.x, w12,
                       fmaf(f2.y, w13, fmaf(f2.z, w14, f2.w * w15)))));
            float d2 = fmaf(f1.z, w20, fmaf(f1.w, w21, fmaf(f2.x, w22,
                       fmaf(f2.y, w23, fmaf(f2.z, w24, f2.w * w25)))));
            float d3 = fmaf(f1.z, w30, fmaf(f1.w, w31, fmaf(f2.x, w32,
                       fmaf(f2.y, w33, fmaf(f2.z, w34, f2.w * w35)))));

            float m0 = c0 * cur0.x, m1 = c1 * cur0.y, m2 = c2 * cur0.z, m3 = c3 * cur0.w;
            float n0 = d0 * cur1.x, n1 = d1 * cur1.y, n2 = d2 * cur1.z, n3 = d3 * cur1.w;

            float* dst0 = out + (size_t)nodes.x * HIDDEN + hbase;
            asm volatile("red.global.add.L2::cache_hint.v4.f32 [%0], {%1, %2, %3, %4}, %5;"
                         :: "l"(dst0), "f"(m0), "f"(m1), "f"(m2), "f"(m3), "l"(pol)
                         : "memory");
            float* dst1 = out + (size_t)nodes.y * HIDDEN + hbase;
            asm volatile("red.global.add.L2::cache_hint.v4.f32 [%0], {%1, %2, %3, %4}, %5;"
                         :: "l"(dst1), "f"(n0), "f"(n1), "f"(n2), "f"(n3), "l"(pol)
                         : "memory");

            cur0 = nxt0;
            cur1 = nxt1;
        }
    }

    // Odd tail edge (E odd): warp 0 handles it.
    if ((E & 1) && wid == 0) {
        const int e = E - 1;
        int node = idx[e];
        const float2* r2 = reinterpret_cast<const float2*>(rbf) + 3 * (size_t)e;
        float2 g0 = r2[0], g1 = r2[1], g2 = r2[2];
        float4 xv = x4[(size_t)e * (HIDDEN / 4) + lane];

        float c0 = fmaf(g0.x, w00, fmaf(g0.y, w01, fmaf(g1.x, w02,
                   fmaf(g1.y, w03, fmaf(g2.x, w04, g2.y * w05)))));
        float c1 = fmaf(g0.x, w10, fmaf(g0.y, w11, fmaf(g1.x, w12,
                   fmaf(g1.y, w13, fmaf(g2.x, w14, g2.y * w15)))));
        float c2 = fmaf(g0.x, w20, fmaf(g0.y, w21, fmaf(g1.x, w22,
                   fmaf(g1.y, w23, fmaf(g2.x, w24, g2.y * w25)))));
        float c3 = fmaf(g0.x, w30, fmaf(g0.y, w31, fmaf(g1.x, w32,
                   fmaf(g1.y, w33, fmaf(g2.x, w34, g2.y * w35)))));

        float* dst = out + (size_t)node * HIDDEN + hbase;
        asm volatile("red.global.add.L2::cache_hint.v4.f32 [%0], {%1, %2, %3, %4}, %5;"
                     :: "l"(dst), "f"(c0 * xv.x), "f"(c1 * xv.y),
                        "f"(c2 * xv.z), "f"(c3 * xv.w), "l"(pol) : "memory");
    }
}

extern "C" void kernel_launch(void* const* d_in, const int* in_sizes, int n_in,
                              void* d_out, int out_size)
{
    const float* x   = (const float*)d_in[0];   // [E, 128]
    const float* rbf = (const float*)d_in[1];   // [E, 6]
    const float* W   = (const float*)d_in[2];   // [128, 6]
    const int*   idx = (const int*)d_in[3];     // [E] int32
    float*       out = (float*)d_out;           // [num_nodes, 128]

    const int E = in_sizes[0] / HIDDEN;

    // Zero output (poisoned to 0xAA by harness)
    {
        int n4 = out_size / 4;
        int threads = 256;
        int blocks = (n4 + threads - 1) / threads;
        if (blocks > 8192) blocks = 8192;
        zero_out_kernel<<<blocks, threads>>>((float4*)out, n4);
    }

    // Fused compute + scatter-add: 8 CTAs/SM * 148 SMs, 4 warps each.
    {
        int threads = 128;
        int blocks  = 148 * 8;              // 1184 blocks -> 4736 warps
        int pairs = E >> 1;
        int max_blocks = (pairs + 3) / 4;
        if (max_blocks < 1) max_blocks = 1;
        if (blocks > max_blocks) blocks = max_blocks;
        fused_rbf_scatter_kernel<<<blocks, threads>>>(x, rbf, W, idx, out, E);
    }
}